// round 6
// baseline (speedup 1.0000x reference)
#include <cuda_runtime.h>
#include <cstdint>
#include <cstddef>

#define B_    128
#define T_    1024
#define HID_  512
#define VOC_  128
#define EMB_  16
#define NGRP  16      // independent batch groups = clusters
#define GSZ   8       // CTAs per group (cluster size)
#define RPG   8       // batch rows per group
#define JPC   64      // hidden columns per CTA
#define SCANT 256

#define WS_PITCH 65
// dynamic smem: Ws[512*65] + Ps[128*64] + 2 x hsm[512*8]
#define SMEM_SCAN ((HID_*WS_PITCH + VOC_*JPC + 2*HID_*RPG)*4)

// ---- device scratch ----
__device__ float g_P[VOC_*HID_];                    // P[v][j] = emb@W_ih^T + b_ih + b_hh
__device__ float g_hs[(size_t)B_*T_*HID_];          // archived hidden states (256MB)

// ---------------------------------------------------------------------------
// Kernel 0: P[v][j] = emb@W_ih^T + b_ih + b_hh
// ---------------------------------------------------------------------------
__global__ void prep_kernel(const float* __restrict__ emb, const float* __restrict__ W_ih,
                            const float* __restrict__ b_ih, const float* __restrict__ b_hh)
{
    int i = blockIdx.x*256 + threadIdx.x;    // 65536 threads
    int v = i >> 9;
    int j = i & 511;
    float s = b_ih[j] + b_hh[j];
    #pragma unroll
    for (int e = 0; e < EMB_; e++)
        s = fmaf(emb[v*EMB_ + e], W_ih[j*EMB_ + e], s);
    g_P[i] = s;
}

// ---- helpers ----
__device__ __forceinline__ unsigned long long pk64(float x, float y) {
    unsigned long long r; asm("mov.b64 %0, {%1, %2};" : "=l"(r) : "f"(x), "f"(y)); return r;
}
__device__ __forceinline__ void push_dsmem(uint32_t dst, int r,
                                           unsigned long long v01, unsigned long long v23) {
    uint32_t rem;
    asm("mapa.shared::cluster.u32 %0, %1, %2;" : "=r"(rem) : "r"(dst), "r"(r));
    asm volatile("st.shared::cluster.b64 [%0],   %1;" :: "r"(rem), "l"(v01) : "memory");
    asm volatile("st.shared::cluster.b64 [%0+8], %1;" :: "r"(rem), "l"(v23) : "memory");
}

// ---------------------------------------------------------------------------
// Kernel 1: persistent scan, h exchanged via DSMEM (no gmem in the loop).
// 16 clusters x 8 CTAs x 256 thr. Thread (jl, rh, kh): col jl, row-half rh
// (4 rows), K-half kh (256 k). h_new slices pushed to all 8 peers' smem with
// st.shared::cluster.b64; cluster arrive(release)/wait(acquire) per step.
// ---------------------------------------------------------------------------
__global__ void __launch_bounds__(SCANT, 1) __cluster_dims__(GSZ, 1, 1)
scan_kernel(const int* __restrict__ x, const float* __restrict__ W_hh)
{
    extern __shared__ float sm[];
    float* Ws   = sm;                          // [512][65] W slice, k-major padded
    float* Ps   = Ws + HID_*WS_PITCH;          // [128][64] P slice
    float* hsmA = Ps + VOC_*JPC;               // [512][8] staged h, buffer 0
    float* hsmB = hsmA + HID_*RPG;             // [512][8] staged h, buffer 1
    __shared__ float4 redA[2*JPC];             // [rh][jl] K-half-1 partial sums
    __shared__ float4 redB[2*JPC];             // [rh][jl] h_new handoff kh0 -> kh1
    __shared__ int    toks[2][RPG];            // double-buffered tokens

    // smem u32 addresses for DSMEM stores
    uint32_t smem_u32;
    asm("{ .reg .u64 t; cvta.to.shared.u64 t, %1; cvt.u32.u64 %0, t; }"
        : "=r"(smem_u32) : "l"(sm));
    const uint32_t hsmA_u32 = smem_u32 + (HID_*WS_PITCH + VOC_*JPC)*4;
    const uint32_t hsmB_u32 = hsmA_u32 + HID_*RPG*4;

    const int g   = blockIdx.x >> 3;          // group / cluster id
    const int c   = blockIdx.x & 7;           // rank within cluster
    const int j0  = c * JPC;
    const int tid = threadIdx.x;
    const int jl  = tid & 63;                 // column
    const int rh  = (tid >> 6) & 1;           // row half: rows rh*4 .. rh*4+3
    const int kh  = tid >> 7;                 // K half (warp-uniform)
    const int rid = rh*JPC + jl;

    // --- prologue: W slice (pitch-65, conflict-free), P slice, zero h buffers ---
    for (int i = tid; i < JPC*HID_; i += SCANT) {
        int jj = i >> 9, k = i & 511;
        Ws[k*WS_PITCH + jj] = W_hh[(j0 + jj)*HID_ + k];
    }
    for (int i = tid; i < VOC_*JPC; i += SCANT) {
        int v = i >> 6, jj = i & 63;
        Ps[i] = g_P[v*HID_ + j0 + jj];
    }
    #pragma unroll
    for (int i = 0; i < 2*HID_*RPG/SCANT; i++)
        hsmA[tid + i*SCANT] = 0.f;            // zeros both buffers (contiguous)
    if (tid < RPG) toks[0][tid] = x[(g*RPG + tid)*T_];
    __syncthreads();
    asm volatile("barrier.cluster.arrive.aligned;" ::: "memory");
    asm volatile("barrier.cluster.wait.aligned;"   ::: "memory");

    for (int t = 0; t < T_; t++) {
        const float*   cur      = (t & 1) ? hsmB : hsmA;
        const uint32_t next_u32 = (t & 1) ? hsmA_u32 : hsmB_u32;
        const int*     tk       = toks[t & 1];

        // acc over 4 rows; K-half 0 seeds with the P lookup
        float a0, a1, a2, a3;
        if (kh == 0) {
            a0 = Ps[tk[rh*4 + 0]*JPC + jl];
            a1 = Ps[tk[rh*4 + 1]*JPC + jl];
            a2 = Ps[tk[rh*4 + 2]*JPC + jl];
            a3 = Ps[tk[rh*4 + 3]*JPC + jl];
        } else {
            a0 = a1 = a2 = a3 = 0.f;
        }

        const float*  wp = Ws + (kh*256)*WS_PITCH + jl;
        const float4* hp = (const float4*)(cur + kh*256*RPG) + rh;
        #pragma unroll 8
        for (int k = 0; k < 256; k++) {
            float  w  = wp[0];                // 1 wf (32 consecutive lanes)
            float4 h4 = hp[0];                // broadcast LDS.128: 1 wf
            a0 = fmaf(w, h4.x, a0);
            a1 = fmaf(w, h4.y, a1);
            a2 = fmaf(w, h4.z, a2);
            a3 = fmaf(w, h4.w, a3);
            wp += WS_PITCH; hp += 2;
        }

        if (kh) redA[rid] = make_float4(a0, a1, a2, a3);
        __syncthreads();

        const uint32_t dst = next_u32 + (uint32_t)(((j0 + jl)*RPG + rh*4)*4);
        if (!kh) {
            float4 p = redA[rid];
            float4 hn;
            hn.x = tanhf(a0 + p.x);
            hn.y = tanhf(a1 + p.y);
            hn.z = tanhf(a2 + p.z);
            hn.w = tanhf(a3 + p.w);
            redB[rid] = hn;                   // handoff to kh1
            unsigned long long v01 = pk64(hn.x, hn.y), v23 = pk64(hn.z, hn.w);
            #pragma unroll
            for (int r = 0; r < 4; r++) push_dsmem(dst, r, v01, v23);
        }
        __syncthreads();                      // publish redB
        if (kh) {
            float4 hn = redB[rid];
            unsigned long long v01 = pk64(hn.x, hn.y), v23 = pk64(hn.z, hn.w);
            #pragma unroll
            for (int r = 4; r < 8; r++) push_dsmem(dst, r, v01, v23);
            // archive (plain STG; kernel boundary orders it for logits kernel)
            size_t base = ((size_t)(g*RPG + rh*4)*T_ + t)*HID_ + j0 + jl;
            g_hs[base]                     = hn.x;
            g_hs[base + (size_t)T_*HID_]   = hn.y;
            g_hs[base + (size_t)2*T_*HID_] = hn.z;
            g_hs[base + (size_t)3*T_*HID_] = hn.w;
        }
        if (tid < RPG && t + 1 < T_)          // prefetch next tokens
            toks[(t + 1) & 1][tid] = x[(g*RPG + tid)*T_ + t + 1];
        // release own DSMEM pushes; acquire peers'
        asm volatile("barrier.cluster.arrive.aligned;" ::: "memory");
        asm volatile("barrier.cluster.wait.aligned;"   ::: "memory");
    }
}

// ---------------------------------------------------------------------------
// Kernel 2: logits = hs[131072,512] @ W_fc^T[512,128] + b_fc
// ---------------------------------------------------------------------------
__global__ void __launch_bounds__(256)
logits_kernel(const float* __restrict__ W_fc, const float* __restrict__ b_fc,
              float* __restrict__ out)
{
    __shared__ float As [64*33];
    __shared__ float Wsh[128*33];
    const int mb  = blockIdx.x * 64;
    const int tid = threadIdx.x;
    const int tv  = tid & 15;
    const int tm  = tid >> 4;

    float acc[4][8];
    #pragma unroll
    for (int vi = 0; vi < 8; vi++) {
        float bv = b_fc[tv + 16*vi];
        #pragma unroll
        for (int mi = 0; mi < 4; mi++) acc[mi][vi] = bv;
    }

    for (int k0 = 0; k0 < HID_; k0 += 32) {
        #pragma unroll
        for (int i = 0; i < 8; i++) {            // 64x32 A chunk
            int idx = tid + i*256;
            int m = idx >> 5, k = idx & 31;
            As[m*33 + k] = g_hs[(size_t)(mb + m)*HID_ + k0 + k];
        }
        #pragma unroll
        for (int i = 0; i < 16; i++) {           // 128x32 W chunk
            int idx = tid + i*256;
            int v = idx >> 5, k = idx & 31;
            Wsh[v*33 + k] = W_fc[v*HID_ + k0 + k];
        }
        __syncthreads();
        #pragma unroll 8
        for (int k = 0; k < 32; k++) {
            float a[4], w[8];
            #pragma unroll
            for (int mi = 0; mi < 4; mi++) a[mi] = As[(tm*4 + mi)*33 + k];
            #pragma unroll
            for (int vi = 0; vi < 8; vi++) w[vi] = Wsh[(tv + 16*vi)*33 + k];
            #pragma unroll
            for (int mi = 0; mi < 4; mi++)
                #pragma unroll
                for (int vi = 0; vi < 8; vi++)
                    acc[mi][vi] = fmaf(a[mi], w[vi], acc[mi][vi]);
        }
        __syncthreads();
    }
    #pragma unroll
    for (int mi = 0; mi < 4; mi++) {
        size_t row = (size_t)(mb + tm*4 + mi) * VOC_;
        #pragma unroll
        for (int vi = 0; vi < 8; vi++)
            out[row + tv + 16*vi] = acc[mi][vi];
    }
}

// ---------------------------------------------------------------------------
extern "C" void kernel_launch(void* const* d_in, const int* in_sizes, int n_in,
                              void* d_out, int out_size)
{
    const int*   x    = (const int*)  d_in[0];
    const float* emb  = (const float*)d_in[1];
    const float* W_ih = (const float*)d_in[2];
    const float* W_hh = (const float*)d_in[3];
    const float* b_ih = (const float*)d_in[4];
    const float* b_hh = (const float*)d_in[5];
    const float* W_fc = (const float*)d_in[6];
    const float* b_fc = (const float*)d_in[7];
    float* out = (float*)d_out;

    cudaFuncSetAttribute(scan_kernel, cudaFuncAttributeMaxDynamicSharedMemorySize, SMEM_SCAN);

    prep_kernel  <<<256, 256>>>(emb, W_ih, b_ih, b_hh);
    scan_kernel  <<<NGRP*GSZ, SCANT, SMEM_SCAN>>>(x, W_hh);
    logits_kernel<<<(B_*T_)/64, 256>>>(W_fc, b_fc, out);
}

// round 7
// speedup vs baseline: 2.2261x; 2.2261x over previous
#include <cuda_runtime.h>
#include <cstdint>
#include <cstddef>

#define B_    128
#define T_    1024
#define HID_  512
#define VOC_  128
#define EMB_  16
#define NGRP  16      // independent batch groups
#define GSZ   8       // CTAs per group
#define RPG   8       // batch rows per group
#define JPC   64      // hidden columns per CTA
#define SCANT 256

#define WS_PITCH 65
// dynamic smem: Ws[512*65] + Ps[128*64] + hsm[512*8]
#define SMEM_SCAN ((HID_*WS_PITCH + VOC_*JPC + HID_*RPG)*4)

// ---- device scratch ----
__device__ float g_P[VOC_*HID_];                    // P[v][j] = emb@W_ih^T + b_ih + b_hh
__device__ float g_h[2][NGRP][HID_][RPG];           // double-buffered h, [buf][g][j][r]
__device__ float g_hs[(size_t)B_*T_*HID_];          // archived hidden states (256MB)
__device__ int   g_ctr[NGRP];                       // group barrier counters (monotonic)

// ---------------------------------------------------------------------------
// Kernel 0: P[v][j] = emb@W_ih^T + b_ih + b_hh; reset group counters
// ---------------------------------------------------------------------------
__global__ void prep_kernel(const float* __restrict__ emb, const float* __restrict__ W_ih,
                            const float* __restrict__ b_ih, const float* __restrict__ b_hh)
{
    int i = blockIdx.x*256 + threadIdx.x;    // 65536 threads
    if (i < NGRP) g_ctr[i] = 0;
    int v = i >> 9;
    int j = i & 511;
    float s = b_ih[j] + b_hh[j];
    #pragma unroll
    for (int e = 0; e < EMB_; e++)
        s = fmaf(emb[v*EMB_ + e], W_ih[j*EMB_ + e], s);
    g_P[i] = s;
}

// ---------------------------------------------------------------------------
// Kernel 1: persistent scan. 16 groups x 8 CTAs x 256 thr. NO clusters.
// Exchange = R1's proven path: STG -> threadfence -> atomic group barrier ->
// __ldcv restage. Compute = (jl, rh, kh) map: col jl, row-half rh (4 rows),
// K-half kh (256 k) -> crossbar 4096 wf/step, FMA 4096 cyc/SMSP.
// ---------------------------------------------------------------------------
__global__ void __launch_bounds__(SCANT, 1)
scan_kernel(const int* __restrict__ x, const float* __restrict__ W_hh)
{
    extern __shared__ float sm[];
    float* Ws  = sm;                          // [512][65] W slice, k-major padded
    float* Ps  = Ws + HID_*WS_PITCH;          // [128][64] P slice
    float* hsm = Ps + VOC_*JPC;               // [512][8]  staged h (k-major, rows inner)
    __shared__ float4 redA[2*JPC];            // [rh][jl] K-half-1 partial sums
    __shared__ int    toks[RPG];

    const int cta = blockIdx.x;
    const int g   = cta >> 3;                 // group id
    const int c   = cta & 7;                  // CTA within group
    const int j0  = c * JPC;
    const int tid = threadIdx.x;
    const int jl  = tid & 63;                 // column
    const int rh  = (tid >> 6) & 1;           // row half: rows rh*4 .. rh*4+3
    const int kh  = tid >> 7;                 // K half (warp-uniform)
    const int rid = rh*JPC + jl;

    // --- prologue: W slice (pitch-65, conflict-free), P slice, zero h0 slice ---
    for (int i = tid; i < JPC*HID_; i += SCANT) {
        int jj = i >> 9, k = i & 511;
        Ws[k*WS_PITCH + jj] = W_hh[(j0 + jj)*HID_ + k];
    }
    for (int i = tid; i < VOC_*JPC; i += SCANT) {
        int v = i >> 6, jj = i & 63;
        Ps[i] = g_P[v*HID_ + j0 + jj];
    }
    if (tid < 128)
        ((float4*)&g_h[0][g][j0][0])[tid] = make_float4(0.f, 0.f, 0.f, 0.f);
    __threadfence();
    __syncthreads();

    int target = GSZ;
    if (tid == 0) {
        atomicAdd(&g_ctr[g], 1);
        while (*(volatile int*)&g_ctr[g] < target) { }
    }
    __syncthreads();
    target += GSZ;

    const float4* hgsrc0 = (const float4*)&g_h[0][g][0][0];
    const float4* hgsrc1 = (const float4*)&g_h[1][g][0][0];

    for (int t = 0; t < T_; t++) {
        // stage full group h (16KB) from L2 (.cv: never trust L1 here)
        const float4* src = (t & 1) ? hgsrc1 : hgsrc0;
        float4* dst4 = (float4*)hsm;
        #pragma unroll
        for (int i = 0; i < 4; i++)
            dst4[tid + i*SCANT] = __ldcv(src + tid + i*SCANT);
        if (tid < RPG) toks[tid] = x[(g*RPG + tid)*T_ + t];
        __syncthreads();

        // acc over 4 rows; K-half 0 seeds with the P lookup
        float a0, a1, a2, a3;
        if (kh == 0) {
            a0 = Ps[toks[rh*4 + 0]*JPC + jl];
            a1 = Ps[toks[rh*4 + 1]*JPC + jl];
            a2 = Ps[toks[rh*4 + 2]*JPC + jl];
            a3 = Ps[toks[rh*4 + 3]*JPC + jl];
        } else {
            a0 = a1 = a2 = a3 = 0.f;
        }

        const float*  wp = Ws + (kh*256)*WS_PITCH + jl;
        const float4* hp = (const float4*)(hsm + kh*256*RPG) + rh;
        #pragma unroll 8
        for (int k = 0; k < 256; k++) {
            float  w  = wp[0];                // 1 wf (32 consecutive lanes)
            float4 h4 = hp[0];                // broadcast LDS.128: 1 wf
            a0 = fmaf(w, h4.x, a0);
            a1 = fmaf(w, h4.y, a1);
            a2 = fmaf(w, h4.z, a2);
            a3 = fmaf(w, h4.w, a3);
            wp += WS_PITCH; hp += 2;
        }

        if (kh) redA[rid] = make_float4(a0, a1, a2, a3);
        __syncthreads();

        if (!kh) {
            float4 p = redA[rid];
            float4 hn;
            hn.x = tanhf(a0 + p.x);
            hn.y = tanhf(a1 + p.y);
            hn.z = tanhf(a2 + p.z);
            hn.w = tanhf(a3 + p.w);
            // publish next-step state + archive (both before the fence, as in R1)
            *(float4*)&g_h[(t & 1) ^ 1][g][j0 + jl][rh*4] = hn;
            size_t base = ((size_t)(g*RPG + rh*4)*T_ + t)*HID_ + j0 + jl;
            g_hs[base]                     = hn.x;
            g_hs[base + (size_t)T_*HID_]   = hn.y;
            g_hs[base + (size_t)2*T_*HID_] = hn.z;
            g_hs[base + (size_t)3*T_*HID_] = hn.w;
        }
        __threadfence();
        __syncthreads();
        if (tid == 0) {
            atomicAdd(&g_ctr[g], 1);
            while (*(volatile int*)&g_ctr[g] < target) { }
        }
        __syncthreads();
        target += GSZ;
    }
}

// ---------------------------------------------------------------------------
// Kernel 2: logits = hs[131072,512] @ W_fc^T[512,128] + b_fc
// ---------------------------------------------------------------------------
__global__ void __launch_bounds__(256)
logits_kernel(const float* __restrict__ W_fc, const float* __restrict__ b_fc,
              float* __restrict__ out)
{
    __shared__ float As [64*33];
    __shared__ float Wsh[128*33];
    const int mb  = blockIdx.x * 64;
    const int tid = threadIdx.x;
    const int tv  = tid & 15;
    const int tm  = tid >> 4;

    float acc[4][8];
    #pragma unroll
    for (int vi = 0; vi < 8; vi++) {
        float bv = b_fc[tv + 16*vi];
        #pragma unroll
        for (int mi = 0; mi < 4; mi++) acc[mi][vi] = bv;
    }

    for (int k0 = 0; k0 < HID_; k0 += 32) {
        #pragma unroll
        for (int i = 0; i < 8; i++) {            // 64x32 A chunk
            int idx = tid + i*256;
            int m = idx >> 5, k = idx & 31;
            As[m*33 + k] = g_hs[(size_t)(mb + m)*HID_ + k0 + k];
        }
        #pragma unroll
        for (int i = 0; i < 16; i++) {           // 128x32 W chunk
            int idx = tid + i*256;
            int v = idx >> 5, k = idx & 31;
            Wsh[v*33 + k] = W_fc[v*HID_ + k0 + k];
        }
        __syncthreads();
        #pragma unroll 8
        for (int k = 0; k < 32; k++) {
            float a[4], w[8];
            #pragma unroll
            for (int mi = 0; mi < 4; mi++) a[mi] = As[(tm*4 + mi)*33 + k];
            #pragma unroll
            for (int vi = 0; vi < 8; vi++) w[vi] = Wsh[(tv + 16*vi)*33 + k];
            #pragma unroll
            for (int mi = 0; mi < 4; mi++)
                #pragma unroll
                for (int vi = 0; vi < 8; vi++)
                    acc[mi][vi] = fmaf(a[mi], w[vi], acc[mi][vi]);
        }
        __syncthreads();
    }
    #pragma unroll
    for (int mi = 0; mi < 4; mi++) {
        size_t row = (size_t)(mb + tm*4 + mi) * VOC_;
        #pragma unroll
        for (int vi = 0; vi < 8; vi++)
            out[row + tv + 16*vi] = acc[mi][vi];
    }
}

// ---------------------------------------------------------------------------
extern "C" void kernel_launch(void* const* d_in, const int* in_sizes, int n_in,
                              void* d_out, int out_size)
{
    const int*   x    = (const int*)  d_in[0];
    const float* emb  = (const float*)d_in[1];
    const float* W_ih = (const float*)d_in[2];
    const float* W_hh = (const float*)d_in[3];
    const float* b_ih = (const float*)d_in[4];
    const float* b_hh = (const float*)d_in[5];
    const float* W_fc = (const float*)d_in[6];
    const float* b_fc = (const float*)d_in[7];
    float* out = (float*)d_out;

    cudaFuncSetAttribute(scan_kernel, cudaFuncAttributeMaxDynamicSharedMemorySize, SMEM_SCAN);

    prep_kernel  <<<256, 256>>>(emb, W_ih, b_ih, b_hh);
    scan_kernel  <<<NGRP*GSZ, SCANT, SMEM_SCAN>>>(x, W_hh);
    logits_kernel<<<(B_*T_)/64, 256>>>(W_fc, b_fc, out);
}